// round 15
// baseline (speedup 1.0000x reference)
#include <cuda_runtime.h>
#include <cuda_fp16.h>
#include <mma.h>

using namespace nvcuda;

#define N_NODES 100000
#define E_MAX   3400000
#define F 128
#define SCAN_NBLK ((N_NODES + 1023) / 1024)   // 98

// ---- static device scratch (allocation-free requirement) ----
__device__ __align__(16) __half g_h0[N_NODES * F];    // hidden states, fp16
__device__ __align__(16) __half g_h1[N_NODES * F];
__device__ __align__(16) __half g_xh[N_NODES * F];    // x converted to fp16
__device__ __align__(16) __half g_g16[N_NODES * F];   // fp16 GEMM payload
__device__ __align__(16) unsigned g_q8[N_NODES * 32]; // int8 payload (4/uint)
__device__ __align__(16) __half g_wh[3 * F * F];      // W1..W3 in fp16
__device__ float  g_g [N_NODES * 32];                 // layer-4 logits (fp32)
__device__ int    g_scale[4];                         // per-layer max|payload| (float bits)
__device__ float  g_dinv[N_NODES];
__device__ int    g_cnt[N_NODES];
__device__ int    g_pos[N_NODES];
__device__ int    g_rowptr[N_NODES + 1];
__device__ int    g_col[E_MAX];
__device__ int    g_bsum[128];
__device__ int    g_boff[128];

__device__ __forceinline__ const __half* pickA(int s) {
    return s < 0 ? g_xh : (s == 0 ? g_h0 : g_h1);
}
__device__ __forceinline__ __half* pick(int s) { return s == 0 ? g_h0 : g_h1; }

struct alignas(16) Half8 { __half2 a, b, c, d; };

// ---- packed f32x2 FMA helpers (gemm32) ----
__device__ __forceinline__ void ffma2(unsigned long long& d,
                                      unsigned long long a, unsigned long long b) {
    asm("fma.rn.f32x2 %0, %1, %2, %0;" : "+l"(d) : "l"(a), "l"(b));
}
__device__ __forceinline__ unsigned long long pack2(float x, float y) {
    unsigned long long r;
    asm("mov.b64 %0, {%1, %2};" : "=l"(r) : "f"(x), "f"(y));
    return r;
}
__device__ __forceinline__ void unpack2(unsigned long long v, float& x, float& y) {
    unsigned lo, hi;
    asm("mov.b64 {%0, %1}, %2;" : "=r"(lo), "=r"(hi) : "l"(v));
    x = __uint_as_float(lo); y = __uint_as_float(hi);
}

__device__ __forceinline__ Half8 to_h8(float4 a0, float4 a1) {
    Half8 h;
    h.a = __floats2half2_rn(a0.x, a0.y);
    h.b = __floats2half2_rn(a0.z, a0.w);
    h.c = __floats2half2_rn(a1.x, a1.y);
    h.d = __floats2half2_rn(a1.z, a1.w);
    return h;
}

// ---- cp.async helpers ----
__device__ __forceinline__ unsigned smem_u32(const void* p) {
    return (unsigned)__cvta_generic_to_shared(p);
}
__device__ __forceinline__ void cp16(unsigned dst, const void* src, bool pred) {
    int sz = pred ? 16 : 0;
    asm volatile("cp.async.ca.shared.global [%0], [%1], 16, %2;\n"
                 :: "r"(dst), "l"(src), "r"(sz));
}
#define CP_COMMIT() asm volatile("cp.async.commit_group;\n" ::: "memory")
#define CP_WAIT(N)  asm volatile("cp.async.wait_group %0;\n" :: "n"(N) : "memory")

// ---------------- prep: zero CSR counters + scales, convert x / W1..3 to fp16 ----

__global__ void k_prep(const float* __restrict__ x,
                       const float* __restrict__ W1,
                       const float* __restrict__ W2,
                       const float* __restrict__ W3) {
    long long i = (long long)blockIdx.x * blockDim.x + threadIdx.x;
    long long base = i * 8;
    if (base < (long long)N_NODES * F) {
        float4 a0 = *(const float4*)&x[base];
        float4 a1 = *(const float4*)&x[base + 4];
        *(Half8*)&g_xh[base] = to_h8(a0, a1);
    }
    if (i < 3 * 2048) {
        int w = (int)(i >> 11);
        int off = ((int)i & 2047) * 8;
        const float* W = (w == 0) ? W1 : (w == 1) ? W2 : W3;
        float4 b0 = *(const float4*)&W[off];
        float4 b1 = *(const float4*)&W[off + 4];
        *(Half8*)&g_wh[w * F * F + off] = to_h8(b0, b1);
    }
    if (i < N_NODES) { g_cnt[i] = 0; g_pos[i] = 0; }
    if (i < 4) g_scale[i] = 0;
}

// ---------------- CSR construction (edge_index is int32) ----------------

__global__ void k_count(const int* __restrict__ ei, int E) {
    int e = blockIdx.x * blockDim.x + threadIdx.x;
    if (e < E) {
        int d = ei[E + e];
        if ((unsigned)d < N_NODES) atomicAdd(&g_cnt[d], 1);
    }
}

__global__ void k_dinv() {
    int i = blockIdx.x * blockDim.x + threadIdx.x;
    if (i < N_NODES) {
        float deg = (float)(g_cnt[i] + 1);   // +1 self loop
        g_dinv[i] = rsqrtf(deg);
    }
}

__global__ __launch_bounds__(1024) void k_scan1() {
    __shared__ int wsum[32];
    int tid = threadIdx.x, lane = tid & 31, wid = tid >> 5;
    int i = blockIdx.x * 1024 + tid;
    int v = (i < N_NODES) ? g_cnt[i] : 0;
    int x = v;
    #pragma unroll
    for (int off = 1; off < 32; off <<= 1) {
        int t = __shfl_up_sync(0xffffffffu, x, off);
        if (lane >= off) x += t;
    }
    if (lane == 31) wsum[wid] = x;
    __syncthreads();
    if (wid == 0) {
        int w = wsum[lane];
        #pragma unroll
        for (int off = 1; off < 32; off <<= 1) {
            int t = __shfl_up_sync(0xffffffffu, w, off);
            if (lane >= off) w += t;
        }
        wsum[lane] = w;
    }
    __syncthreads();
    int excl = x - v + (wid ? wsum[wid - 1] : 0);
    if (i < N_NODES) g_rowptr[i] = excl;
    if (tid == 0) g_bsum[blockIdx.x] = wsum[31];
}

__global__ __launch_bounds__(128) void k_scan2() {
    __shared__ int s[128];
    int tid = threadIdx.x;
    int v = (tid < SCAN_NBLK) ? g_bsum[tid] : 0;
    s[tid] = v;
    __syncthreads();
    #pragma unroll
    for (int off = 1; off < 128; off <<= 1) {
        int t = (tid >= off) ? s[tid - off] : 0;
        __syncthreads();
        s[tid] += t;
        __syncthreads();
    }
    g_boff[tid] = s[tid] - v;          // exclusive
    if (tid == 127) g_rowptr[N_NODES] = s[127];
}

__global__ __launch_bounds__(1024) void k_scan3() {
    int i = blockIdx.x * 1024 + threadIdx.x;
    if (i < N_NODES) g_rowptr[i] += g_boff[blockIdx.x];
}

__global__ void k_fill(const int* __restrict__ ei, int E) {
    int e = blockIdx.x * blockDim.x + threadIdx.x;
    if (e < E) {
        int s = ei[e];
        int d = ei[E + e];
        if ((unsigned)s < N_NODES && (unsigned)d < N_NODES) {
            int p = atomicAdd(&g_pos[d], 1);
            g_col[g_rowptr[d] + p] = s;
        }
    }
}

// ---------------- GEMM (tensor cores, cp.async double-buffered) -------------------
// Also block-reduces max|payload| into g_scale[widx] for int8 quantization.

__global__ __launch_bounds__(256) void k_gemm128(int srcsel, int widx, int M) {
    const __half* __restrict__ A  = pickA(srcsel);
    const __half* __restrict__ Wh = g_wh + widx * F * F;
    __shared__ __half As[2][128][24];    // ld=24 (48B)
    __shared__ __half Bs[2][16][136];    // ld=136 (272B)
    __shared__ float  Cs[8][16 * 20];    // epilogue staging
    __shared__ float  smax[256];

    int tid  = threadIdx.x;
    int wid  = tid >> 5;
    int lane = tid & 31;
    int row0 = blockIdx.x * 128;
    int wr = wid >> 1;
    int wc = wid & 1;

    int ar = tid >> 1;
    int ac = (tid & 1) * 8;
    int br = tid >> 4;
    int bc = (tid & 15) * 8;
    bool avalid = (row0 + ar) < M;
    const __half* Arow = A + (long long)(row0 + (avalid ? ar : 0)) * F + ac;

    #pragma unroll
    for (int s = 0; s < 2; s++) {
        cp16(smem_u32(&As[s][ar][ac]), Arow + s * 16, avalid);
        cp16(smem_u32(&Bs[s][br][bc]), Wh + (s * 16 + br) * F + bc, true);
        CP_COMMIT();
    }

    wmma::fragment<wmma::accumulator, 16, 16, 16, float> c[2][4];
    #pragma unroll
    for (int i = 0; i < 2; i++)
        #pragma unroll
        for (int j = 0; j < 4; j++) wmma::fill_fragment(c[i][j], 0.f);

    #pragma unroll
    for (int kk = 0; kk < 8; kk++) {
        if (kk < 7) { CP_WAIT(1); } else { CP_WAIT(0); }
        __syncthreads();
        int cur = kk & 1;
        wmma::fragment<wmma::matrix_a, 16, 16, 16, __half, wmma::row_major> af[2];
        wmma::fragment<wmma::matrix_b, 16, 16, 16, __half, wmma::row_major> bf[4];
        #pragma unroll
        for (int i = 0; i < 2; i++)
            wmma::load_matrix_sync(af[i], &As[cur][wr * 32 + i * 16][0], 24);
        #pragma unroll
        for (int j = 0; j < 4; j++)
            wmma::load_matrix_sync(bf[j], &Bs[cur][0][wc * 64 + j * 16], 136);
        #pragma unroll
        for (int i = 0; i < 2; i++)
            #pragma unroll
            for (int j = 0; j < 4; j++)
                wmma::mma_sync(c[i][j], af[i], bf[j], c[i][j]);
        __syncthreads();
        if (kk < 6) {
            cp16(smem_u32(&As[cur][ar][ac]), Arow + (kk + 2) * 16, avalid);
            cp16(smem_u32(&Bs[cur][br][bc]), Wh + ((kk + 2) * 16 + br) * F + bc, true);
            CP_COMMIT();
        }
    }

    float mv = 0.f;
    #pragma unroll
    for (int i = 0; i < 2; i++) {
        #pragma unroll
        for (int j = 0; j < 4; j++) {
            wmma::store_matrix_sync(&Cs[wid][0], c[i][j], 20, wmma::mem_row_major);
            __syncwarp();
            int rr = lane >> 1;
            int c0 = (lane & 1) * 8;
            int grow = row0 + wr * 32 + i * 16 + rr;
            if (grow < M) {
                float d = g_dinv[grow];
                const float* src = &Cs[wid][rr * 20 + c0];
                float v0 = src[0] * d, v1 = src[1] * d, v2 = src[2] * d, v3 = src[3] * d;
                float v4 = src[4] * d, v5 = src[5] * d, v6 = src[6] * d, v7 = src[7] * d;
                mv = fmaxf(mv, fmaxf(fmaxf(fabsf(v0), fabsf(v1)),
                                     fmaxf(fabsf(v2), fabsf(v3))));
                mv = fmaxf(mv, fmaxf(fmaxf(fabsf(v4), fabsf(v5)),
                                     fmaxf(fabsf(v6), fabsf(v7))));
                Half8 h;
                h.a = __floats2half2_rn(v0, v1);
                h.b = __floats2half2_rn(v2, v3);
                h.c = __floats2half2_rn(v4, v5);
                h.d = __floats2half2_rn(v6, v7);
                *(Half8*)&g_g16[(long long)grow * 128 + wc * 64 + j * 16 + c0] = h;
            }
            __syncwarp();
        }
    }
    // block max-reduce -> one atomic per block
    smax[tid] = mv;
    __syncthreads();
    #pragma unroll
    for (int s = 128; s > 0; s >>= 1) {
        if (tid < s) smax[tid] = fmaxf(smax[tid], smax[tid + s]);
        __syncthreads();
    }
    if (tid == 0) atomicMax(&g_scale[widx], __float_as_int(smax[0]));
}

// ---------------- Quantize payload with the GLOBAL layer scale -------------------
// thread per 4 values (uint2 of fp16 -> 4B int8).

__global__ __launch_bounds__(256) void k_quant(int widx) {
    long long i = (long long)blockIdx.x * blockDim.x + threadIdx.x;
    if (i >= (long long)N_NODES * 32) return;
    float gmax = __int_as_float(g_scale[widx]);
    float inv = (gmax > 0.f) ? 127.f / gmax : 0.f;
    uint2 v = ((const uint2*)g_g16)[i];
    float2 a = __half22float2(*(__half2*)&v.x);
    float2 b = __half22float2(*(__half2*)&v.y);
    int q0 = __float2int_rn(a.x * inv);
    int q1 = __float2int_rn(a.y * inv);
    int q2 = __float2int_rn(b.x * inv);
    int q3 = __float2int_rn(b.y * inv);
    g_q8[i] = (q0 & 0xff) | ((q1 & 0xff) << 8) | ((q2 & 0xff) << 16) | (q3 << 24);
}

// ---------------- GEMM 128x32 (last layer), fp16 A -> fp32 FFMA2 -> g_g [M,32] ----

__global__ __launch_bounds__(256) void k_gemm32(int srcsel,
                                                const float* __restrict__ W, int M) {
    const __half* __restrict__ A = pick(srcsel);
    __shared__ float As[16][128];
    __shared__ float Bs[16][32];
    int tid = threadIdx.x;
    int row0 = blockIdx.x * 128;
    int tr = tid >> 3;
    int tc = tid & 7;
    unsigned long long acc[2][4];
    #pragma unroll
    for (int p = 0; p < 2; p++)
        #pragma unroll
        for (int j = 0; j < 4; j++) acc[p][j] = 0ull;

    for (int k0 = 0; k0 < 128; k0 += 16) {
        #pragma unroll
        for (int it = 0; it < 2; it++) {
            int idx = tid + it * 256;
            int r  = idx >> 2;
            int kc = (idx & 3) * 4;
            int grow = row0 + r;
            float4 a;
            if (grow < M) {
                uint2 hv = *(const uint2*)&A[(long long)grow * 128 + k0 + kc];
                float2 p0 = __half22float2(*(__half2*)&hv.x);
                float2 p1 = __half22float2(*(__half2*)&hv.y);
                a = make_float4(p0.x, p0.y, p1.x, p1.y);
            } else {
                a = make_float4(0.f, 0.f, 0.f, 0.f);
            }
            As[kc + 0][r] = a.x; As[kc + 1][r] = a.y;
            As[kc + 2][r] = a.z; As[kc + 3][r] = a.w;
        }
        if (tid < 128) {
            int r = tid >> 3;
            int c = (tid & 7) * 4;
            *(float4*)&Bs[r][c] = *(const float4*)&W[(k0 + r) * 32 + c];
        }
        __syncthreads();
        #pragma unroll
        for (int k = 0; k < 16; k++) {
            const unsigned long long* ap =
                (const unsigned long long*)&As[k][tr * 4];
            unsigned long long a01 = ap[0], a23 = ap[1];
            float b0[4];
            *(float4*)&b0[0] = *(const float4*)&Bs[k][tc * 4];
            #pragma unroll
            for (int j = 0; j < 4; j++) {
                unsigned long long bb = pack2(b0[j], b0[j]);
                ffma2(acc[0][j], a01, bb);
                ffma2(acc[1][j], a23, bb);
            }
        }
        __syncthreads();
    }
    #pragma unroll
    for (int p = 0; p < 2; p++) {
        float lo[4], hi[4];
        #pragma unroll
        for (int j = 0; j < 4; j++) unpack2(acc[p][j], lo[j], hi[j]);
        int r0 = row0 + tr * 4 + 2 * p;
        if (r0 < M) {
            float d = g_dinv[r0];
            float4 o = make_float4(lo[0] * d, lo[1] * d, lo[2] * d, lo[3] * d);
            *(float4*)&g_g[(long long)r0 * 32 + tc * 4] = o;
        }
        if (r0 + 1 < M) {
            float d = g_dinv[r0 + 1];
            float4 o = make_float4(hi[0] * d, hi[1] * d, hi[2] * d, hi[3] * d);
            *(float4*)&g_g[(long long)(r0 + 1) * 32 + tc * 4] = o;
        }
    }
}

// ---------------- Aggregation (128-wide, int8 + global scale, DP4A) --------------
// warp per node; indices staged in smem; 4B LDGs batched x8; int32 accumulate,
// ONE scale multiply per node at the end. Self-loop from fp16 (exact).

__global__ __launch_bounds__(256) void k_agg128(const float* __restrict__ bias,
                                                int dstsel, int widx) {
    __shared__ int sidx[8][32];
    __half* __restrict__ out = pick(dstsel);
    int wid = threadIdx.x >> 5, lane = threadIdx.x & 31;
    int gw = blockIdx.x * 8 + wid;
    if (gw >= N_NODES) return;

    uint2 self = ((const uint2*)g_g16)[(long long)gw * 32 + lane];
    float2 f0 = __half22float2(*(__half2*)&self.x);
    float2 f1 = __half22float2(*(__half2*)&self.y);

    int a0 = 0, a1 = 0, a2 = 0, a3 = 0;
    int s0 = g_rowptr[gw], s1 = g_rowptr[gw + 1];
    for (int base = s0; base < s1; base += 32) {
        int n = min(32, s1 - base);
        sidx[wid][lane] = (base + lane < s1) ? g_col[base + lane] : 0;
        __syncwarp();
        int j = 0;
        for (; j + 8 <= n; j += 8) {
            unsigned v[8];
            #pragma unroll
            for (int t = 0; t < 8; t++) {
                int s = sidx[wid][j + t];
                v[t] = __ldg(&g_q8[(long long)s * 32 + lane]);
            }
            #pragma unroll
            for (int t = 0; t < 8; t++) {
                a0 = __dp4a((int)v[t], 0x00000001, a0);
                a1 = __dp4a((int)v[t], 0x00000100, a1);
                a2 = __dp4a((int)v[t], 0x00010000, a2);
                a3 = __dp4a((int)v[t], 0x01000000, a3);
            }
        }
        for (; j < n; j++) {
            int s = sidx[wid][j];
            unsigned v = __ldg(&g_q8[(long long)s * 32 + lane]);
            a0 = __dp4a((int)v, 0x00000001, a0);
            a1 = __dp4a((int)v, 0x00000100, a1);
            a2 = __dp4a((int)v, 0x00010000, a2);
            a3 = __dp4a((int)v, 0x01000000, a3);
        }
        __syncwarp();
    }
    float gmax = __int_as_float(g_scale[widx]);
    float sc = (gmax > 0.f) ? gmax / 127.f : 0.f;
    float accx = f0.x + sc * (float)a0;
    float accy = f0.y + sc * (float)a1;
    float accz = f1.x + sc * (float)a2;
    float accw = f1.y + sc * (float)a3;

    float d = g_dinv[gw];
    float4 b = ((const float4*)bias)[lane];
    float rx = fmaxf(d * accx + b.x, 0.f);
    float ry = fmaxf(d * accy + b.y, 0.f);
    float rz = fmaxf(d * accz + b.z, 0.f);
    float rw = fmaxf(d * accw + b.w, 0.f);
    uint2 o;
    *(__half2*)&o.x = __floats2half2_rn(rx, ry);
    *(__half2*)&o.y = __floats2half2_rn(rz, rw);
    ((uint2*)out)[(long long)gw * 32 + lane] = o;
}

// ---------------- Aggregation (32-wide, fp32) + log_softmax fused ----------------

__global__ __launch_bounds__(256) void k_agg32_lsm(const float* __restrict__ bias,
                                                   float* __restrict__ out) {
    __shared__ int sidx[8][32];
    int wid = threadIdx.x >> 5, lane = threadIdx.x & 31;
    int gw = blockIdx.x * 8 + wid;
    if (gw >= N_NODES) return;
    float acc = g_g[(long long)gw * 32 + lane];
    int s0 = g_rowptr[gw], s1 = g_rowptr[gw + 1];
    for (int base = s0; base < s1; base += 32) {
        int n = min(32, s1 - base);
        sidx[wid][lane] = (base + lane < s1) ? g_col[base + lane] : 0;
        __syncwarp();
        int j = 0;
        for (; j + 8 <= n; j += 8) {
            float v[8];
            #pragma unroll
            for (int t = 0; t < 8; t++) {
                int s = sidx[wid][j + t];
                v[t] = __ldg(&g_g[(long long)s * 32 + lane]);
            }
            #pragma unroll
            for (int t = 0; t < 8; t++) acc += v[t];
        }
        for (; j < n; j++) {
            int s = sidx[wid][j];
            acc += __ldg(&g_g[(long long)s * 32 + lane]);
        }
        __syncwarp();
    }
    float v = g_dinv[gw] * acc + bias[lane];
    float mx = v;
    #pragma unroll
    for (int off = 16; off; off >>= 1)
        mx = fmaxf(mx, __shfl_xor_sync(0xffffffffu, mx, off));
    float e = expf(v - mx);
    float sum = e;
    #pragma unroll
    for (int off = 16; off; off >>= 1)
        sum += __shfl_xor_sync(0xffffffffu, sum, off);
    out[(long long)gw * 32 + lane] = v - mx - logf(sum);
}

// ---------------- launch ----------------

extern "C" void kernel_launch(void* const* d_in, const int* in_sizes, int n_in,
                              void* d_out, int out_size) {
    const float* x  = (const float*)d_in[0];
    const int*   ei = (const int*)d_in[1];       // int32
    const float* W1 = (const float*)d_in[2]; const float* b1 = (const float*)d_in[3];
    const float* W2 = (const float*)d_in[4]; const float* b2 = (const float*)d_in[5];
    const float* W3 = (const float*)d_in[6]; const float* b3 = (const float*)d_in[7];
    const float* W4 = (const float*)d_in[8]; const float* b4 = (const float*)d_in[9];
    float* out = (float*)d_out;
    int E = in_sizes[1] / 2;
    if (E > E_MAX) E = E_MAX;

    const int TB = 256;
    int gN = (N_NODES + TB - 1) / TB;
    int gE = (E + TB - 1) / TB;
    int gGemm = (N_NODES + 127) / 128;
    int gAgg  = (N_NODES + 7) / 8;
    int gPrep = ((N_NODES * F / 8) + TB - 1) / TB;   // 6250
    int gQ    = ((N_NODES * 32) + TB - 1) / TB;      // 12500

    // prep (zero + fp16 conversions) + CSR build; gemm128 is 4th launch (profiled)
    k_prep   <<<gPrep, TB>>>(x, W1, W2, W3);
    k_count  <<<gE, TB>>>(ei, E);
    k_dinv   <<<gN, TB>>>();
    k_gemm128<<<gGemm, TB>>>(-1, 0, N_NODES);       // layer-1 GEMM (x -> g_g16)
    k_scan1  <<<SCAN_NBLK, 1024>>>();
    k_scan2  <<<1, 128>>>();
    k_scan3  <<<SCAN_NBLK, 1024>>>();
    k_fill   <<<gE, TB>>>(ei, E);

    // layer 1
    k_quant  <<<gQ, TB>>>(0);
    k_agg128 <<<gAgg, TB>>>(b1, 0, 0);
    // layer 2
    k_gemm128<<<gGemm, TB>>>(0, 1, N_NODES);
    k_quant  <<<gQ, TB>>>(1);
    k_agg128 <<<gAgg, TB>>>(b2, 1, 1);
    // layer 3
    k_gemm128<<<gGemm, TB>>>(1, 2, N_NODES);
    k_quant  <<<gQ, TB>>>(2);
    k_agg128 <<<gAgg, TB>>>(b3, 0, 2);
    // layer 4 (transform first -> 32-wide aggregation, fp32) + log_softmax
    k_gemm32 <<<gGemm, TB>>>(0, W4, N_NODES);
    k_agg32_lsm<<<gAgg, TB>>>(b4, out);
}

// round 16
// speedup vs baseline: 1.0574x; 1.0574x over previous
#include <cuda_runtime.h>
#include <cuda_fp16.h>
#include <mma.h>

using namespace nvcuda;

#define N_NODES 100000
#define E_MAX   3400000
#define F 128
#define SCAN_NBLK ((N_NODES + 1023) / 1024)   // 98

// ---- static device scratch (allocation-free requirement) ----
__device__ __align__(16) __half g_h0[N_NODES * F];    // hidden states, fp16
__device__ __align__(16) __half g_h1[N_NODES * F];
__device__ __align__(16) __half g_xh[N_NODES * F];    // x converted to fp16
__device__ __align__(16) __half g_g16[N_NODES * F];   // fp16 gather payload
__device__ __align__(16) __half g_wh[3 * F * F];      // W1..W3 in fp16
__device__ float  g_g [N_NODES * 32];                 // layer-4 logits (fp32)
__device__ float  g_dinv[N_NODES];
__device__ int    g_cnt[N_NODES];
__device__ int    g_pos[N_NODES];
__device__ int    g_rowptr[N_NODES + 1];
__device__ int    g_col[E_MAX];
__device__ int    g_bsum[128];
__device__ int    g_boff[128];

__device__ __forceinline__ const __half* pickA(int s) {
    return s < 0 ? g_xh : (s == 0 ? g_h0 : g_h1);
}
__device__ __forceinline__ __half* pick(int s) { return s == 0 ? g_h0 : g_h1; }

struct alignas(16) Half8 { __half2 a, b, c, d; };

// ---- packed f32x2 FMA helpers (gemm32) ----
__device__ __forceinline__ void ffma2(unsigned long long& d,
                                      unsigned long long a, unsigned long long b) {
    asm("fma.rn.f32x2 %0, %1, %2, %0;" : "+l"(d) : "l"(a), "l"(b));
}
__device__ __forceinline__ unsigned long long pack2(float x, float y) {
    unsigned long long r;
    asm("mov.b64 %0, {%1, %2};" : "=l"(r) : "f"(x), "f"(y));
    return r;
}
__device__ __forceinline__ void unpack2(unsigned long long v, float& x, float& y) {
    unsigned lo, hi;
    asm("mov.b64 {%0, %1}, %2;" : "=r"(lo), "=r"(hi) : "l"(v));
    x = __uint_as_float(lo); y = __uint_as_float(hi);
}

__device__ __forceinline__ Half8 to_h8(float4 a0, float4 a1) {
    Half8 h;
    h.a = __floats2half2_rn(a0.x, a0.y);
    h.b = __floats2half2_rn(a0.z, a0.w);
    h.c = __floats2half2_rn(a1.x, a1.y);
    h.d = __floats2half2_rn(a1.z, a1.w);
    return h;
}

// ---- cp.async helpers ----
__device__ __forceinline__ unsigned smem_u32(const void* p) {
    return (unsigned)__cvta_generic_to_shared(p);
}
__device__ __forceinline__ void cp16(unsigned dst, const void* src, bool pred) {
    int sz = pred ? 16 : 0;
    asm volatile("cp.async.ca.shared.global [%0], [%1], 16, %2;\n"
                 :: "r"(dst), "l"(src), "r"(sz));
}
#define CP_COMMIT() asm volatile("cp.async.commit_group;\n" ::: "memory")
#define CP_WAIT(N)  asm volatile("cp.async.wait_group %0;\n" :: "n"(N) : "memory")

// ---------------- prep: zero CSR counters, convert x and W1..3 to fp16 -----------

__global__ void k_prep(const float* __restrict__ x,
                       const float* __restrict__ W1,
                       const float* __restrict__ W2,
                       const float* __restrict__ W3) {
    long long i = (long long)blockIdx.x * blockDim.x + threadIdx.x;
    long long base = i * 8;
    if (base < (long long)N_NODES * F) {
        float4 a0 = *(const float4*)&x[base];
        float4 a1 = *(const float4*)&x[base + 4];
        *(Half8*)&g_xh[base] = to_h8(a0, a1);
    }
    if (i < 3 * 2048) {
        int w = (int)(i >> 11);
        int off = ((int)i & 2047) * 8;
        const float* W = (w == 0) ? W1 : (w == 1) ? W2 : W3;
        float4 b0 = *(const float4*)&W[off];
        float4 b1 = *(const float4*)&W[off + 4];
        *(Half8*)&g_wh[w * F * F + off] = to_h8(b0, b1);
    }
    if (i < N_NODES) { g_cnt[i] = 0; g_pos[i] = 0; }
}

// ---------------- CSR construction (edge_index is int32) ----------------

__global__ void k_count(const int* __restrict__ ei, int E) {
    int e = blockIdx.x * blockDim.x + threadIdx.x;
    if (e < E) {
        int d = ei[E + e];
        if ((unsigned)d < N_NODES) atomicAdd(&g_cnt[d], 1);
    }
}

__global__ void k_dinv() {
    int i = blockIdx.x * blockDim.x + threadIdx.x;
    if (i < N_NODES) {
        float deg = (float)(g_cnt[i] + 1);   // +1 self loop
        g_dinv[i] = rsqrtf(deg);
    }
}

__global__ __launch_bounds__(1024) void k_scan1() {
    __shared__ int wsum[32];
    int tid = threadIdx.x, lane = tid & 31, wid = tid >> 5;
    int i = blockIdx.x * 1024 + tid;
    int v = (i < N_NODES) ? g_cnt[i] : 0;
    int x = v;
    #pragma unroll
    for (int off = 1; off < 32; off <<= 1) {
        int t = __shfl_up_sync(0xffffffffu, x, off);
        if (lane >= off) x += t;
    }
    if (lane == 31) wsum[wid] = x;
    __syncthreads();
    if (wid == 0) {
        int w = wsum[lane];
        #pragma unroll
        for (int off = 1; off < 32; off <<= 1) {
            int t = __shfl_up_sync(0xffffffffu, w, off);
            if (lane >= off) w += t;
        }
        wsum[lane] = w;
    }
    __syncthreads();
    int excl = x - v + (wid ? wsum[wid - 1] : 0);
    if (i < N_NODES) g_rowptr[i] = excl;
    if (tid == 0) g_bsum[blockIdx.x] = wsum[31];
}

__global__ __launch_bounds__(128) void k_scan2() {
    __shared__ int s[128];
    int tid = threadIdx.x;
    int v = (tid < SCAN_NBLK) ? g_bsum[tid] : 0;
    s[tid] = v;
    __syncthreads();
    #pragma unroll
    for (int off = 1; off < 128; off <<= 1) {
        int t = (tid >= off) ? s[tid - off] : 0;
        __syncthreads();
        s[tid] += t;
        __syncthreads();
    }
    g_boff[tid] = s[tid] - v;          // exclusive
    if (tid == 127) g_rowptr[N_NODES] = s[127];
}

__global__ __launch_bounds__(1024) void k_scan3() {
    int i = blockIdx.x * 1024 + threadIdx.x;
    if (i < N_NODES) g_rowptr[i] += g_boff[blockIdx.x];
}

__global__ void k_fill(const int* __restrict__ ei, int E) {
    int e = blockIdx.x * blockDim.x + threadIdx.x;
    if (e < E) {
        int s = ei[e];
        int d = ei[E + e];
        if ((unsigned)s < N_NODES && (unsigned)d < N_NODES) {
            int p = atomicAdd(&g_pos[d], 1);
            g_col[g_rowptr[d] + p] = s;
        }
    }
}

// ---------------- GEMM (tensor cores, cp.async double-buffered) -------------------
// __launch_bounds__(256,2): cap regs at 128 so 2 blocks/SM fit (R15 showed
// occ 24% -> 28us vs occ 12% -> 34us).

__global__ __launch_bounds__(256, 2) void k_gemm128(int srcsel, int widx, int M) {
    const __half* __restrict__ A  = pickA(srcsel);
    const __half* __restrict__ Wh = g_wh + widx * F * F;
    __shared__ __half As[2][128][24];    // ld=24 (48B)
    __shared__ __half Bs[2][16][136];    // ld=136 (272B)
    __shared__ float  Cs[8][16 * 20];    // epilogue staging

    int tid  = threadIdx.x;
    int wid  = tid >> 5;
    int lane = tid & 31;
    int row0 = blockIdx.x * 128;
    int wr = wid >> 1;
    int wc = wid & 1;

    int ar = tid >> 1;
    int ac = (tid & 1) * 8;
    int br = tid >> 4;
    int bc = (tid & 15) * 8;
    bool avalid = (row0 + ar) < M;
    const __half* Arow = A + (long long)(row0 + (avalid ? ar : 0)) * F + ac;

    #pragma unroll
    for (int s = 0; s < 2; s++) {
        cp16(smem_u32(&As[s][ar][ac]), Arow + s * 16, avalid);
        cp16(smem_u32(&Bs[s][br][bc]), Wh + (s * 16 + br) * F + bc, true);
        CP_COMMIT();
    }

    wmma::fragment<wmma::accumulator, 16, 16, 16, float> c[2][4];
    #pragma unroll
    for (int i = 0; i < 2; i++)
        #pragma unroll
        for (int j = 0; j < 4; j++) wmma::fill_fragment(c[i][j], 0.f);

    #pragma unroll
    for (int kk = 0; kk < 8; kk++) {
        if (kk < 7) { CP_WAIT(1); } else { CP_WAIT(0); }
        __syncthreads();
        int cur = kk & 1;
        wmma::fragment<wmma::matrix_a, 16, 16, 16, __half, wmma::row_major> af[2];
        wmma::fragment<wmma::matrix_b, 16, 16, 16, __half, wmma::row_major> bf[4];
        #pragma unroll
        for (int i = 0; i < 2; i++)
            wmma::load_matrix_sync(af[i], &As[cur][wr * 32 + i * 16][0], 24);
        #pragma unroll
        for (int j = 0; j < 4; j++)
            wmma::load_matrix_sync(bf[j], &Bs[cur][0][wc * 64 + j * 16], 136);
        #pragma unroll
        for (int i = 0; i < 2; i++)
            #pragma unroll
            for (int j = 0; j < 4; j++)
                wmma::mma_sync(c[i][j], af[i], bf[j], c[i][j]);
        __syncthreads();
        if (kk < 6) {
            cp16(smem_u32(&As[cur][ar][ac]), Arow + (kk + 2) * 16, avalid);
            cp16(smem_u32(&Bs[cur][br][bc]), Wh + ((kk + 2) * 16 + br) * F + bc, true);
            CP_COMMIT();
        }
    }

    #pragma unroll
    for (int i = 0; i < 2; i++) {
        #pragma unroll
        for (int j = 0; j < 4; j++) {
            wmma::store_matrix_sync(&Cs[wid][0], c[i][j], 20, wmma::mem_row_major);
            __syncwarp();
            int rr = lane >> 1;
            int c0 = (lane & 1) * 8;
            int grow = row0 + wr * 32 + i * 16 + rr;
            if (grow < M) {
                float d = g_dinv[grow];
                const float* src = &Cs[wid][rr * 20 + c0];
                Half8 h;
                h.a = __floats2half2_rn(src[0] * d, src[1] * d);
                h.b = __floats2half2_rn(src[2] * d, src[3] * d);
                h.c = __floats2half2_rn(src[4] * d, src[5] * d);
                h.d = __floats2half2_rn(src[6] * d, src[7] * d);
                *(Half8*)&g_g16[(long long)grow * 128 + wc * 64 + j * 16 + c0] = h;
            }
            __syncwarp();
        }
    }
}

// ---------------- GEMM 128x32 (last layer), fp16 A -> fp32 FFMA2 -> g_g [M,32] ----

__global__ __launch_bounds__(256) void k_gemm32(int srcsel,
                                                const float* __restrict__ W, int M) {
    const __half* __restrict__ A = pick(srcsel);
    __shared__ float As[16][128];
    __shared__ float Bs[16][32];
    int tid = threadIdx.x;
    int row0 = blockIdx.x * 128;
    int tr = tid >> 3;
    int tc = tid & 7;
    unsigned long long acc[2][4];
    #pragma unroll
    for (int p = 0; p < 2; p++)
        #pragma unroll
        for (int j = 0; j < 4; j++) acc[p][j] = 0ull;

    for (int k0 = 0; k0 < 128; k0 += 16) {
        #pragma unroll
        for (int it = 0; it < 2; it++) {
            int idx = tid + it * 256;
            int r  = idx >> 2;
            int kc = (idx & 3) * 4;
            int grow = row0 + r;
            float4 a;
            if (grow < M) {
                uint2 hv = *(const uint2*)&A[(long long)grow * 128 + k0 + kc];
                float2 p0 = __half22float2(*(__half2*)&hv.x);
                float2 p1 = __half22float2(*(__half2*)&hv.y);
                a = make_float4(p0.x, p0.y, p1.x, p1.y);
            } else {
                a = make_float4(0.f, 0.f, 0.f, 0.f);
            }
            As[kc + 0][r] = a.x; As[kc + 1][r] = a.y;
            As[kc + 2][r] = a.z; As[kc + 3][r] = a.w;
        }
        if (tid < 128) {
            int r = tid >> 3;
            int c = (tid & 7) * 4;
            *(float4*)&Bs[r][c] = *(const float4*)&W[(k0 + r) * 32 + c];
        }
        __syncthreads();
        #pragma unroll
        for (int k = 0; k < 16; k++) {
            const unsigned long long* ap =
                (const unsigned long long*)&As[k][tr * 4];
            unsigned long long a01 = ap[0], a23 = ap[1];
            float b0[4];
            *(float4*)&b0[0] = *(const float4*)&Bs[k][tc * 4];
            #pragma unroll
            for (int j = 0; j < 4; j++) {
                unsigned long long bb = pack2(b0[j], b0[j]);
                ffma2(acc[0][j], a01, bb);
                ffma2(acc[1][j], a23, bb);
            }
        }
        __syncthreads();
    }
    #pragma unroll
    for (int p = 0; p < 2; p++) {
        float lo[4], hi[4];
        #pragma unroll
        for (int j = 0; j < 4; j++) unpack2(acc[p][j], lo[j], hi[j]);
        int r0 = row0 + tr * 4 + 2 * p;
        if (r0 < M) {
            float d = g_dinv[r0];
            float4 o = make_float4(lo[0] * d, lo[1] * d, lo[2] * d, lo[3] * d);
            *(float4*)&g_g[(long long)r0 * 32 + tc * 4] = o;
        }
        if (r0 + 1 < M) {
            float d = g_dinv[r0 + 1];
            float4 o = make_float4(hi[0] * d, hi[1] * d, hi[2] * d, hi[3] * d);
            *(float4*)&g_g[(long long)(r0 + 1) * 32 + tc * 4] = o;
        }
    }
}

// ---------------- Aggregation (128-wide, fp16, warp per node, batch 16) -----------

__global__ __launch_bounds__(256) void k_agg128(const float* __restrict__ bias,
                                                int dstsel) {
    __shared__ int sidx[8][32];
    __half* __restrict__ out = pick(dstsel);
    int wid = threadIdx.x >> 5, lane = threadIdx.x & 31;
    int gw = blockIdx.x * 8 + wid;
    if (gw >= N_NODES) return;
    const uint2* __restrict__ gg = (const uint2*)g_g16;

    uint2 self = gg[(long long)gw * 32 + lane];
    float2 f0 = __half22float2(*(__half2*)&self.x);
    float2 f1 = __half22float2(*(__half2*)&self.y);
    float4 acc = make_float4(f0.x, f0.y, f1.x, f1.y);

    int s0 = g_rowptr[gw], s1 = g_rowptr[gw + 1];
    for (int base = s0; base < s1; base += 32) {
        int n = min(32, s1 - base);
        sidx[wid][lane] = (base + lane < s1) ? g_col[base + lane] : 0;
        __syncwarp();
        int j = 0;
        for (; j + 16 <= n; j += 16) {
            uint2 v[16];
            #pragma unroll
            for (int t = 0; t < 16; t++) {
                int s = sidx[wid][j + t];
                v[t] = __ldg(&gg[(long long)s * 32 + lane]);
            }
            #pragma unroll
            for (int t = 0; t < 16; t++) {
                float2 a = __half22float2(*(__half2*)&v[t].x);
                float2 b = __half22float2(*(__half2*)&v[t].y);
                acc.x += a.x; acc.y += a.y; acc.z += b.x; acc.w += b.y;
            }
        }
        for (; j + 8 <= n; j += 8) {
            uint2 v[8];
            #pragma unroll
            for (int t = 0; t < 8; t++) {
                int s = sidx[wid][j + t];
                v[t] = __ldg(&gg[(long long)s * 32 + lane]);
            }
            #pragma unroll
            for (int t = 0; t < 8; t++) {
                float2 a = __half22float2(*(__half2*)&v[t].x);
                float2 b = __half22float2(*(__half2*)&v[t].y);
                acc.x += a.x; acc.y += a.y; acc.z += b.x; acc.w += b.y;
            }
        }
        for (; j < n; j++) {
            int s = sidx[wid][j];
            uint2 v = __ldg(&gg[(long long)s * 32 + lane]);
            float2 a = __half22float2(*(__half2*)&v.x);
            float2 b = __half22float2(*(__half2*)&v.y);
            acc.x += a.x; acc.y += a.y; acc.z += b.x; acc.w += b.y;
        }
        __syncwarp();
    }
    float d = g_dinv[gw];
    float4 b = ((const float4*)bias)[lane];
    float rx = fmaxf(d * acc.x + b.x, 0.f);
    float ry = fmaxf(d * acc.y + b.y, 0.f);
    float rz = fmaxf(d * acc.z + b.z, 0.f);
    float rw = fmaxf(d * acc.w + b.w, 0.f);
    uint2 o;
    *(__half2*)&o.x = __floats2half2_rn(rx, ry);
    *(__half2*)&o.y = __floats2half2_rn(rz, rw);
    ((uint2*)out)[(long long)gw * 32 + lane] = o;
}

// ---------------- Aggregation (32-wide, fp32) + log_softmax fused ----------------

__global__ __launch_bounds__(256) void k_agg32_lsm(const float* __restrict__ bias,
                                                   float* __restrict__ out) {
    __shared__ int sidx[8][32];
    int wid = threadIdx.x >> 5, lane = threadIdx.x & 31;
    int gw = blockIdx.x * 8 + wid;
    if (gw >= N_NODES) return;
    float acc = g_g[(long long)gw * 32 + lane];
    int s0 = g_rowptr[gw], s1 = g_rowptr[gw + 1];
    for (int base = s0; base < s1; base += 32) {
        int n = min(32, s1 - base);
        sidx[wid][lane] = (base + lane < s1) ? g_col[base + lane] : 0;
        __syncwarp();
        int j = 0;
        for (; j + 8 <= n; j += 8) {
            float v[8];
            #pragma unroll
            for (int t = 0; t < 8; t++) {
                int s = sidx[wid][j + t];
                v[t] = __ldg(&g_g[(long long)s * 32 + lane]);
            }
            #pragma unroll
            for (int t = 0; t < 8; t++) acc += v[t];
        }
        for (; j < n; j++) {
            int s = sidx[wid][j];
            acc += __ldg(&g_g[(long long)s * 32 + lane]);
        }
        __syncwarp();
    }
    float v = g_dinv[gw] * acc + bias[lane];
    float mx = v;
    #pragma unroll
    for (int off = 16; off; off >>= 1)
        mx = fmaxf(mx, __shfl_xor_sync(0xffffffffu, mx, off));
    float e = expf(v - mx);
    float sum = e;
    #pragma unroll
    for (int off = 16; off; off >>= 1)
        sum += __shfl_xor_sync(0xffffffffu, sum, off);
    out[(long long)gw * 32 + lane] = v - mx - logf(sum);
}

// ---------------- launch ----------------

extern "C" void kernel_launch(void* const* d_in, const int* in_sizes, int n_in,
                              void* d_out, int out_size) {
    const float* x  = (const float*)d_in[0];
    const int*   ei = (const int*)d_in[1];       // int32
    const float* W1 = (const float*)d_in[2]; const float* b1 = (const float*)d_in[3];
    const float* W2 = (const float*)d_in[4]; const float* b2 = (const float*)d_in[5];
    const float* W3 = (const float*)d_in[6]; const float* b3 = (const float*)d_in[7];
    const float* W4 = (const float*)d_in[8]; const float* b4 = (const float*)d_in[9];
    float* out = (float*)d_out;
    int E = in_sizes[1] / 2;
    if (E > E_MAX) E = E_MAX;

    const int TB = 256;
    int gN = (N_NODES + TB - 1) / TB;
    int gE = (E + TB - 1) / TB;
    int gGemm = (N_NODES + 127) / 128;
    int gAgg  = (N_NODES + 7) / 8;
    int gPrep = ((N_NODES * F / 8) + TB - 1) / TB;   // 6250

    // prep (zero + fp16 conversions) + CSR build; gemm128 is 4th launch (profiled)
    k_prep   <<<gPrep, TB>>>(x, W1, W2, W3);
    k_count  <<<gE, TB>>>(ei, E);
    k_dinv   <<<gN, TB>>>();
    k_gemm128<<<gGemm, TB>>>(-1, 0, N_NODES);       // layer-1 GEMM (x -> g_g16)
    k_scan1  <<<SCAN_NBLK, 1024>>>();
    k_scan2  <<<1, 128>>>();
    k_scan3  <<<SCAN_NBLK, 1024>>>();
    k_fill   <<<gE, TB>>>(ei, E);

    // layer 1 aggregation
    k_agg128 <<<gAgg, TB>>>(b1, 0);
    // layer 2
    k_gemm128<<<gGemm, TB>>>(0, 1, N_NODES);
    k_agg128 <<<gAgg, TB>>>(b2, 1);
    // layer 3
    k_gemm128<<<gGemm, TB>>>(1, 2, N_NODES);
    k_agg128 <<<gAgg, TB>>>(b3, 0);
    // layer 4 (transform first -> 32-wide aggregation, fp32) + log_softmax
    k_gemm32 <<<gGemm, TB>>>(0, W4, N_NODES);
    k_agg32_lsm<<<gAgg, TB>>>(b4, out);
}

// round 17
// speedup vs baseline: 1.1114x; 1.0511x over previous
#include <cuda_runtime.h>
#include <cuda_fp16.h>
#include <mma.h>

using namespace nvcuda;

#define N_NODES 100000
#define E_MAX   3400000
#define F 128
#define SCAN_NBLK ((N_NODES + 1023) / 1024)   // 98

// ---- static device scratch (allocation-free requirement) ----
__device__ __align__(16) __half g_h0[N_NODES * F];    // hidden states, fp16
__device__ __align__(16) __half g_h1[N_NODES * F];
__device__ __align__(16) __half g_xh[N_NODES * F];    // x converted to fp16
__device__ __align__(16) __half g_g16[N_NODES * F];   // fp16 gather payload
__device__ __align__(16) __half g_wh[3 * F * F + F * 32];  // W1..W3 + W4 in fp16
__device__ float  g_g [N_NODES * 32];                 // layer-4 logits (fp32)
__device__ float  g_dinv[N_NODES];
__device__ int    g_cnt[N_NODES];
__device__ int    g_pos[N_NODES];
__device__ int    g_rowptr[N_NODES + 1];
__device__ int    g_col[E_MAX];
__device__ int    g_bsum[128];
__device__ int    g_boff[128];

__device__ __forceinline__ const __half* pickA(int s) {
    return s < 0 ? g_xh : (s == 0 ? g_h0 : g_h1);
}
__device__ __forceinline__ __half* pick(int s) { return s == 0 ? g_h0 : g_h1; }

struct alignas(16) Half8 { __half2 a, b, c, d; };

__device__ __forceinline__ Half8 to_h8(float4 a0, float4 a1) {
    Half8 h;
    h.a = __floats2half2_rn(a0.x, a0.y);
    h.b = __floats2half2_rn(a0.z, a0.w);
    h.c = __floats2half2_rn(a1.x, a1.y);
    h.d = __floats2half2_rn(a1.z, a1.w);
    return h;
}

// ---- cp.async helpers ----
__device__ __forceinline__ unsigned smem_u32(const void* p) {
    return (unsigned)__cvta_generic_to_shared(p);
}
__device__ __forceinline__ void cp16(unsigned dst, const void* src, bool pred) {
    int sz = pred ? 16 : 0;
    asm volatile("cp.async.ca.shared.global [%0], [%1], 16, %2;\n"
                 :: "r"(dst), "l"(src), "r"(sz));
}
#define CP_COMMIT() asm volatile("cp.async.commit_group;\n" ::: "memory")
#define CP_WAIT(N)  asm volatile("cp.async.wait_group %0;\n" :: "n"(N) : "memory")

// ---------------- prep: zero CSR counters, convert x and W1..4 to fp16 -----------

__global__ void k_prep(const float* __restrict__ x,
                       const float* __restrict__ W1,
                       const float* __restrict__ W2,
                       const float* __restrict__ W3,
                       const float* __restrict__ W4) {
    long long i = (long long)blockIdx.x * blockDim.x + threadIdx.x;
    long long base = i * 8;
    if (base < (long long)N_NODES * F) {
        float4 a0 = *(const float4*)&x[base];
        float4 a1 = *(const float4*)&x[base + 4];
        *(Half8*)&g_xh[base] = to_h8(a0, a1);
    }
    if (i < 3 * 2048) {
        int w = (int)(i >> 11);
        int off = ((int)i & 2047) * 8;
        const float* W = (w == 0) ? W1 : (w == 1) ? W2 : W3;
        float4 b0 = *(const float4*)&W[off];
        float4 b1 = *(const float4*)&W[off + 4];
        *(Half8*)&g_wh[w * F * F + off] = to_h8(b0, b1);
    } else if (i < 3 * 2048 + 512) {
        int off = ((int)i - 3 * 2048) * 8;
        float4 b0 = *(const float4*)&W4[off];
        float4 b1 = *(const float4*)&W4[off + 4];
        *(Half8*)&g_wh[3 * F * F + off] = to_h8(b0, b1);
    }
    if (i < N_NODES) { g_cnt[i] = 0; g_pos[i] = 0; }
}

// ---------------- CSR construction (edge_index is int32) ----------------

__global__ void k_count(const int* __restrict__ ei, int E) {
    int e = blockIdx.x * blockDim.x + threadIdx.x;
    if (e < E) {
        int d = ei[E + e];
        if ((unsigned)d < N_NODES) atomicAdd(&g_cnt[d], 1);
    }
}

// scan stage 1 (+ dinv computed inline from the same g_cnt load)
__global__ __launch_bounds__(1024) void k_scan1() {
    __shared__ int wsum[32];
    int tid = threadIdx.x, lane = tid & 31, wid = tid >> 5;
    int i = blockIdx.x * 1024 + tid;
    int v = (i < N_NODES) ? g_cnt[i] : 0;
    if (i < N_NODES) g_dinv[i] = rsqrtf((float)(v + 1));   // +1 self loop
    int x = v;
    #pragma unroll
    for (int off = 1; off < 32; off <<= 1) {
        int t = __shfl_up_sync(0xffffffffu, x, off);
        if (lane >= off) x += t;
    }
    if (lane == 31) wsum[wid] = x;
    __syncthreads();
    if (wid == 0) {
        int w = wsum[lane];
        #pragma unroll
        for (int off = 1; off < 32; off <<= 1) {
            int t = __shfl_up_sync(0xffffffffu, w, off);
            if (lane >= off) w += t;
        }
        wsum[lane] = w;
    }
    __syncthreads();
    int excl = x - v + (wid ? wsum[wid - 1] : 0);
    if (i < N_NODES) g_rowptr[i] = excl;
    if (tid == 0) g_bsum[blockIdx.x] = wsum[31];
}

__global__ __launch_bounds__(128) void k_scan2() {
    __shared__ int s[128];
    int tid = threadIdx.x;
    int v = (tid < SCAN_NBLK) ? g_bsum[tid] : 0;
    s[tid] = v;
    __syncthreads();
    #pragma unroll
    for (int off = 1; off < 128; off <<= 1) {
        int t = (tid >= off) ? s[tid - off] : 0;
        __syncthreads();
        s[tid] += t;
        __syncthreads();
    }
    g_boff[tid] = s[tid] - v;          // exclusive
    if (tid == 127) g_rowptr[N_NODES] = s[127];
}

__global__ __launch_bounds__(1024) void k_scan3() {
    int i = blockIdx.x * 1024 + threadIdx.x;
    if (i < N_NODES) g_rowptr[i] += g_boff[blockIdx.x];
}

__global__ void k_fill(const int* __restrict__ ei, int E) {
    int e = blockIdx.x * blockDim.x + threadIdx.x;
    if (e < E) {
        int s = ei[e];
        int d = ei[E + e];
        if ((unsigned)s < N_NODES && (unsigned)d < N_NODES) {
            int p = atomicAdd(&g_pos[d], 1);
            g_col[g_rowptr[d] + p] = s;
        }
    }
}

// ---------------- GEMM (tensor cores, cp.async 3-stage pipeline) -------------------

__global__ __launch_bounds__(256, 2) void k_gemm128(int srcsel, int widx, int M) {
    const __half* __restrict__ A  = pickA(srcsel);
    const __half* __restrict__ Wh = g_wh + widx * F * F;
    __shared__ __half As[3][128][24];    // ld=24 (48B)
    __shared__ __half Bs[3][16][136];    // ld=136 (272B)
    __shared__ float  Cs[8][16 * 20];    // epilogue staging

    int tid  = threadIdx.x;
    int wid  = tid >> 5;
    int lane = tid & 31;
    int row0 = blockIdx.x * 128;
    int wr = wid >> 1;
    int wc = wid & 1;

    int ar = tid >> 1;
    int ac = (tid & 1) * 8;
    int br = tid >> 4;
    int bc = (tid & 15) * 8;
    bool avalid = (row0 + ar) < M;
    const __half* Arow = A + (long long)(row0 + (avalid ? ar : 0)) * F + ac;

    #pragma unroll
    for (int s = 0; s < 3; s++) {
        cp16(smem_u32(&As[s][ar][ac]), Arow + s * 16, avalid);
        cp16(smem_u32(&Bs[s][br][bc]), Wh + (s * 16 + br) * F + bc, true);
        CP_COMMIT();
    }

    wmma::fragment<wmma::accumulator, 16, 16, 16, float> c[2][4];
    #pragma unroll
    for (int i = 0; i < 2; i++)
        #pragma unroll
        for (int j = 0; j < 4; j++) wmma::fill_fragment(c[i][j], 0.f);

    #pragma unroll
    for (int kk = 0; kk < 8; kk++) {
        if (kk <= 5)      { CP_WAIT(2); }
        else if (kk == 6) { CP_WAIT(1); }
        else              { CP_WAIT(0); }
        __syncthreads();
        int cur = kk % 3;
        wmma::fragment<wmma::matrix_a, 16, 16, 16, __half, wmma::row_major> af[2];
        wmma::fragment<wmma::matrix_b, 16, 16, 16, __half, wmma::row_major> bf[4];
        #pragma unroll
        for (int i = 0; i < 2; i++)
            wmma::load_matrix_sync(af[i], &As[cur][wr * 32 + i * 16][0], 24);
        #pragma unroll
        for (int j = 0; j < 4; j++)
            wmma::load_matrix_sync(bf[j], &Bs[cur][0][wc * 64 + j * 16], 136);
        #pragma unroll
        for (int i = 0; i < 2; i++)
            #pragma unroll
            for (int j = 0; j < 4; j++)
                wmma::mma_sync(c[i][j], af[i], bf[j], c[i][j]);
        __syncthreads();
        if (kk < 5) {
            cp16(smem_u32(&As[cur][ar][ac]), Arow + (kk + 3) * 16, avalid);
            cp16(smem_u32(&Bs[cur][br][bc]), Wh + ((kk + 3) * 16 + br) * F + bc, true);
            CP_COMMIT();
        }
    }

    #pragma unroll
    for (int i = 0; i < 2; i++) {
        #pragma unroll
        for (int j = 0; j < 4; j++) {
            wmma::store_matrix_sync(&Cs[wid][0], c[i][j], 20, wmma::mem_row_major);
            __syncwarp();
            int rr = lane >> 1;
            int c0 = (lane & 1) * 8;
            int grow = row0 + wr * 32 + i * 16 + rr;
            if (grow < M) {
                float d = g_dinv[grow];
                const float* src = &Cs[wid][rr * 20 + c0];
                Half8 h;
                h.a = __floats2half2_rn(src[0] * d, src[1] * d);
                h.b = __floats2half2_rn(src[2] * d, src[3] * d);
                h.c = __floats2half2_rn(src[4] * d, src[5] * d);
                h.d = __floats2half2_rn(src[6] * d, src[7] * d);
                *(Half8*)&g_g16[(long long)grow * 128 + wc * 64 + j * 16 + c0] = h;
            }
            __syncwarp();
        }
    }
}

// ---------------- GEMM 128x32 (last layer, WMMA, fp16 W4) -> g_g fp32 [M,32] ------
// Block = 128 rows x 32 cols, 8 warps, warp = 16 rows x 32 cols (2 tiles).

__global__ __launch_bounds__(256, 2) void k_gemm32(int srcsel, int M) {
    const __half* __restrict__ A   = pick(srcsel);
    const __half* __restrict__ W4h = g_wh + 3 * F * F;
    __shared__ __half As[2][128][24];    // ld=24
    __shared__ __half Bs[2][16][40];     // ld=40 (80B, 16B mult)
    __shared__ float  Cs[8][16 * 20];

    int tid  = threadIdx.x;
    int wid  = tid >> 5;
    int lane = tid & 31;
    int row0 = blockIdx.x * 128;

    int ar = tid >> 1;
    int ac = (tid & 1) * 8;
    bool avalid = (row0 + ar) < M;
    const __half* Arow = A + (long long)(row0 + (avalid ? ar : 0)) * F + ac;
    // B staging: 16 rows x 32 cols = 512 halves = 64 chunks of 8
    int bon = (tid < 64);
    int br = tid >> 2;          // 0..15 (for tid<64)
    int bc = (tid & 3) * 8;     // 0,8,16,24

    #pragma unroll
    for (int s = 0; s < 2; s++) {
        cp16(smem_u32(&As[s][ar][ac]), Arow + s * 16, avalid);
        if (bon) cp16(smem_u32(&Bs[s][br][bc]), W4h + (s * 16 + br) * 32 + bc, true);
        CP_COMMIT();
    }

    wmma::fragment<wmma::accumulator, 16, 16, 16, float> c2[2];
    #pragma unroll
    for (int j = 0; j < 2; j++) wmma::fill_fragment(c2[j], 0.f);

    #pragma unroll
    for (int kk = 0; kk < 8; kk++) {
        if (kk < 7) { CP_WAIT(1); } else { CP_WAIT(0); }
        __syncthreads();
        int cur = kk & 1;
        wmma::fragment<wmma::matrix_a, 16, 16, 16, __half, wmma::row_major> af;
        wmma::fragment<wmma::matrix_b, 16, 16, 16, __half, wmma::row_major> bf[2];
        wmma::load_matrix_sync(af, &As[cur][wid * 16][0], 24);
        #pragma unroll
        for (int j = 0; j < 2; j++)
            wmma::load_matrix_sync(bf[j], &Bs[cur][0][j * 16], 40);
        #pragma unroll
        for (int j = 0; j < 2; j++)
            wmma::mma_sync(c2[j], af, bf[j], c2[j]);
        __syncthreads();
        if (kk < 6) {
            cp16(smem_u32(&As[cur][ar][ac]), Arow + (kk + 2) * 16, avalid);
            if (bon) cp16(smem_u32(&Bs[cur][br][bc]),
                          W4h + ((kk + 2) * 16 + br) * 32 + bc, true);
            CP_COMMIT();
        }
    }

    #pragma unroll
    for (int j = 0; j < 2; j++) {
        wmma::store_matrix_sync(&Cs[wid][0], c2[j], 20, wmma::mem_row_major);
        __syncwarp();
        int rr = lane >> 1;
        int c0 = (lane & 1) * 8;
        int grow = row0 + wid * 16 + rr;
        if (grow < M) {
            float d = g_dinv[grow];
            const float* src = &Cs[wid][rr * 20 + c0];
            float4 o0 = make_float4(src[0] * d, src[1] * d, src[2] * d, src[3] * d);
            float4 o1 = make_float4(src[4] * d, src[5] * d, src[6] * d, src[7] * d);
            *(float4*)&g_g[(long long)grow * 32 + j * 16 + c0]     = o0;
            *(float4*)&g_g[(long long)grow * 32 + j * 16 + c0 + 4] = o1;
        }
        __syncwarp();
    }
}

// ---------------- Aggregation (128-wide, fp16, warp per node, batch 16) -----------

__global__ __launch_bounds__(256) void k_agg128(const float* __restrict__ bias,
                                                int dstsel) {
    __shared__ int sidx[8][32];
    __half* __restrict__ out = pick(dstsel);
    int wid = threadIdx.x >> 5, lane = threadIdx.x & 31;
    int gw = blockIdx.x * 8 + wid;
    if (gw >= N_NODES) return;
    const uint2* __restrict__ gg = (const uint2*)g_g16;

    uint2 self = gg[(long long)gw * 32 + lane];
    float2 f0 = __half22float2(*(__half2*)&self.x);
    float2 f1 = __half22float2(*(__half2*)&self.y);
    float4 acc = make_float4(f0.x, f0.y, f1.x, f1.y);

    int s0 = g_rowptr[gw], s1 = g_rowptr[gw + 1];
    for (int base = s0; base < s1; base += 32) {
        int n = min(32, s1 - base);
        sidx[wid][lane] = (base + lane < s1) ? g_col[base + lane] : 0;
        __syncwarp();
        int j = 0;
        for (; j + 16 <= n; j += 16) {
            uint2 v[16];
            #pragma unroll
            for (int t = 0; t < 16; t++) {
                int s = sidx[wid][j + t];
                v[t] = __ldg(&gg[(long long)s * 32 + lane]);
            }
            #pragma unroll
            for (int t = 0; t < 16; t++) {
                float2 a = __half22float2(*(__half2*)&v[t].x);
                float2 b = __half22float2(*(__half2*)&v[t].y);
                acc.x += a.x; acc.y += a.y; acc.z += b.x; acc.w += b.y;
            }
        }
        for (; j + 8 <= n; j += 8) {
            uint2 v[8];
            #pragma unroll
            for (int t = 0; t < 8; t++) {
                int s = sidx[wid][j + t];
                v[t] = __ldg(&gg[(long long)s * 32 + lane]);
            }
            #pragma unroll
            for (int t = 0; t < 8; t++) {
                float2 a = __half22float2(*(__half2*)&v[t].x);
                float2 b = __half22float2(*(__half2*)&v[t].y);
                acc.x += a.x; acc.y += a.y; acc.z += b.x; acc.w += b.y;
            }
        }
        for (; j < n; j++) {
            int s = sidx[wid][j];
            uint2 v = __ldg(&gg[(long long)s * 32 + lane]);
            float2 a = __half22float2(*(__half2*)&v.x);
            float2 b = __half22float2(*(__half2*)&v.y);
            acc.x += a.x; acc.y += a.y; acc.z += b.x; acc.w += b.y;
        }
        __syncwarp();
    }
    float d = g_dinv[gw];
    float4 b = ((const float4*)bias)[lane];
    float rx = fmaxf(d * acc.x + b.x, 0.f);
    float ry = fmaxf(d * acc.y + b.y, 0.f);
    float rz = fmaxf(d * acc.z + b.z, 0.f);
    float rw = fmaxf(d * acc.w + b.w, 0.f);
    uint2 o;
    *(__half2*)&o.x = __floats2half2_rn(rx, ry);
    *(__half2*)&o.y = __floats2half2_rn(rz, rw);
    ((uint2*)out)[(long long)gw * 32 + lane] = o;
}

// ---------------- Aggregation (32-wide, fp32) + log_softmax fused ----------------

__global__ __launch_bounds__(256) void k_agg32_lsm(const float* __restrict__ bias,
                                                   float* __restrict__ out) {
    __shared__ int sidx[8][32];
    int wid = threadIdx.x >> 5, lane = threadIdx.x & 31;
    int gw = blockIdx.x * 8 + wid;
    if (gw >= N_NODES) return;
    float acc = g_g[(long long)gw * 32 + lane];
    int s0 = g_rowptr[gw], s1 = g_rowptr[gw + 1];
    for (int base = s0; base < s1; base += 32) {
        int n = min(32, s1 - base);
        sidx[wid][lane] = (base + lane < s1) ? g_col[base + lane] : 0;
        __syncwarp();
        int j = 0;
        for (; j + 8 <= n; j += 8) {
            float v[8];
            #pragma unroll
            for (int t = 0; t < 8; t++) {
                int s = sidx[wid][j + t];
                v[t] = __ldg(&g_g[(long long)s * 32 + lane]);
            }
            #pragma unroll
            for (int t = 0; t < 8; t++) acc += v[t];
        }
        for (; j < n; j++) {
            int s = sidx[wid][j];
            acc += __ldg(&g_g[(long long)s * 32 + lane]);
        }
        __syncwarp();
    }
    float v = g_dinv[gw] * acc + bias[lane];
    float mx = v;
    #pragma unroll
    for (int off = 16; off; off >>= 1)
        mx = fmaxf(mx, __shfl_xor_sync(0xffffffffu, mx, off));
    float e = expf(v - mx);
    float sum = e;
    #pragma unroll
    for (int off = 16; off; off >>= 1)
        sum += __shfl_xor_sync(0xffffffffu, sum, off);
    out[(long long)gw * 32 + lane] = v - mx - logf(sum);
}

// ---------------- launch ----------------

extern "C" void kernel_launch(void* const* d_in, const int* in_sizes, int n_in,
                              void* d_out, int out_size) {
    const float* x  = (const float*)d_in[0];
    const int*   ei = (const int*)d_in[1];       // int32
    const float* W1 = (const float*)d_in[2]; const float* b1 = (const float*)d_in[3];
    const float* W2 = (const float*)d_in[4]; const float* b2 = (const float*)d_in[5];
    const float* W3 = (const float*)d_in[6]; const float* b3 = (const float*)d_in[7];
    const float* W4 = (const float*)d_in[8]; const float* b4 = (const float*)d_in[9];
    float* out = (float*)d_out;
    int E = in_sizes[1] / 2;
    if (E > E_MAX) E = E_MAX;

    const int TB = 256;
    int gE = (E + TB - 1) / TB;
    int gGemm = (N_NODES + 127) / 128;
    int gAgg  = (N_NODES + 7) / 8;
    int gPrep = ((N_NODES * F / 8) + TB - 1) / TB;   // 6250

    // prep + CSR build; gemm128 is 4th launch (profiled). scan1 also computes dinv.
    k_prep   <<<gPrep, TB>>>(x, W1, W2, W3, W4);
    k_count  <<<gE, TB>>>(ei, E);
    k_scan1  <<<SCAN_NBLK, 1024>>>();
    k_gemm128<<<gGemm, TB>>>(-1, 0, N_NODES);       // layer-1 GEMM (x -> g_g16)
    k_scan2  <<<1, 128>>>();
    k_scan3  <<<SCAN_NBLK, 1024>>>();
    k_fill   <<<gE, TB>>>(ei, E);

    // layer 1 aggregation
    k_agg128 <<<gAgg, TB>>>(b1, 0);
    // layer 2
    k_gemm128<<<gGemm, TB>>>(0, 1, N_NODES);
    k_agg128 <<<gAgg, TB>>>(b2, 1);
    // layer 3
    k_gemm128<<<gGemm, TB>>>(1, 2, N_NODES);
    k_agg128 <<<gAgg, TB>>>(b3, 0);
    // layer 4 (transform first -> 32-wide aggregation, fp32) + log_softmax
    k_gemm32 <<<gGemm, TB>>>(0, N_NODES);
    k_agg32_lsm<<<gAgg, TB>>>(b4, out);
}